// round 4
// baseline (speedup 1.0000x reference)
#include <cuda_runtime.h>
#include <cuda_bf16.h>

#define D 128
#define D4 32            // D/4 float4s per row
#define MAXN 65536
#define MAXE (1 << 20)
#define EPS 0.1f

// -------- scratch (device globals; no allocation allowed) --------
__device__ int          g_is64;       // 1 if edge_index is int64, 0 if int32
__device__ unsigned int g_or;         // probe reduction
__device__ int   g_cnt[MAXN];         // in-degree (edges only)
__device__ int   g_cursor[MAXN];      // bucket fill cursor
__device__ int   g_off[MAXN + 1];     // CSR offsets
__device__ int   g_csr[MAXE];         // CSR: source node per incoming edge
__device__ float g_al[MAXN];
__device__ float g_ar[MAXN];
__device__ float g_dinv[MAXN];
__device__ float g_agg[(size_t)MAXN * D];

// -------- k0: zero counters + probe accumulator --------
__global__ void k_zero(int N) {
    int i = blockIdx.x * blockDim.x + threadIdx.x;
    if (i < N) { g_cnt[i] = 0; g_cursor[i] = 0; }
    if (i == 0) g_or = 0u;
}

// -------- k_probe: OR odd int32 words of first E pairs.
// int64 layout: those are hi-words of valid node ids -> all 0.
// int32 layout: those are random node ids -> OR != 0 (certain for E=600k).
__global__ void k_probe(const unsigned int* __restrict__ p, int E) {
    unsigned int v = 0;
    for (int i = blockIdx.x * blockDim.x + threadIdx.x; i < E;
         i += gridDim.x * blockDim.x)
        v |= p[2 * i + 1];
    #pragma unroll
    for (int o = 16; o > 0; o >>= 1) v |= __shfl_down_sync(0xFFFFFFFFu, v, o);
    if ((threadIdx.x & 31) == 0 && v) atomicOr(&g_or, v);
}
__global__ void k_setflag() { g_is64 = (g_or == 0u) ? 1 : 0; }

__device__ __forceinline__ int edge_src(const int* __restrict__ p, int E, int i) {
    return g_is64 ? p[2 * i] : p[i];
}
__device__ __forceinline__ int edge_dst(const int* __restrict__ p, int E, int i) {
    return g_is64 ? p[2 * (E + i)] : p[E + i];
}

// -------- k1: count in-degree over edges (int atomics) --------
__global__ void k_count(const int* __restrict__ p, int E) {
    int i = blockIdx.x * blockDim.x + threadIdx.x;
    if (i < E) atomicAdd(&g_cnt[edge_dst(p, E, i)], 1);
}

// -------- k2: per-node al, ar, dinv (one warp per node) --------
__global__ void k_node(const float4* __restrict__ x4,
                       const float4* __restrict__ attl4,
                       const float4* __restrict__ attr4, int N) {
    int warp = (blockIdx.x * blockDim.x + threadIdx.x) >> 5;
    int lane = threadIdx.x & 31;
    if (warp >= N) return;
    float4 xv = x4[(size_t)warp * D4 + lane];
    float4 lv = attl4[lane];
    float4 rv = attr4[lane];
    float pl = xv.x * lv.x + xv.y * lv.y + xv.z * lv.z + xv.w * lv.w;
    float pr = xv.x * rv.x + xv.y * rv.y + xv.z * rv.z + xv.w * rv.w;
    #pragma unroll
    for (int o = 16; o > 0; o >>= 1) {
        pl += __shfl_down_sync(0xFFFFFFFFu, pl, o);
        pr += __shfl_down_sync(0xFFFFFFFFu, pr, o);
    }
    if (lane == 0) {
        g_al[warp] = pl;
        g_ar[warp] = pr;
        g_dinv[warp] = rsqrtf((float)g_cnt[warp] + 1.0f);  // +1 self loop
    }
}

// -------- k3: single-block exclusive scan of g_cnt -> g_off --------
__global__ void k_scan(int N) {
    __shared__ int warp_sums[32];
    int t = threadIdx.x;                 // 1024 threads
    int lane = t & 31, w = t >> 5;
    int chunk = (N + 1023) >> 10;
    int begin = t * chunk;
    int end = begin + chunk; if (end > N) end = N; if (begin > N) begin = N;
    int local = 0;
    for (int i = begin; i < end; i++) local += g_cnt[i];
    int v = local;
    #pragma unroll
    for (int o = 1; o < 32; o <<= 1) {
        int u = __shfl_up_sync(0xFFFFFFFFu, v, o);
        if (lane >= o) v += u;
    }
    if (lane == 31) warp_sums[w] = v;
    __syncthreads();
    if (w == 0) {
        int s = warp_sums[lane];
        #pragma unroll
        for (int o = 1; o < 32; o <<= 1) {
            int u = __shfl_up_sync(0xFFFFFFFFu, s, o);
            if (lane >= o) s += u;
        }
        warp_sums[lane] = s;
    }
    __syncthreads();
    int incl = v + (w > 0 ? warp_sums[w - 1] : 0);
    int run = incl - local;              // exclusive offset for this thread
    for (int i = begin; i < end; i++) { g_off[i] = run; run += g_cnt[i]; }
    if (t == 1023) g_off[N] = run;       // total
}

// -------- k4: bucket scatter -> CSR --------
__global__ void k_build(const int* __restrict__ p, int E) {
    int i = blockIdx.x * blockDim.x + threadIdx.x;
    if (i < E) {
        int r = edge_src(p, E, i);
        int c = edge_dst(p, E, i);
        int pos = atomicAdd(&g_cursor[c], 1);
        g_csr[g_off[c] + pos] = r;
    }
}

// -------- k5: gather-aggregate (warp per node, register acc, no atomics) --
__global__ void k_gather(const float4* __restrict__ x4, int N) {
    int n = (blockIdx.x * blockDim.x + threadIdx.x) >> 5;
    int lane = threadIdx.x & 31;
    if (n >= N) return;
    float dv  = g_dinv[n];
    float arn = g_ar[n];
    float s = EPS + tanhf(g_al[n] + arn) * dv * dv;   // self loop + eps
    float4 xv = x4[(size_t)n * D4 + lane];
    float4 acc = make_float4(xv.x * s, xv.y * s, xv.z * s, xv.w * s);
    int e   = g_off[n];
    int end = g_off[n + 1];
    for (; e < end; e++) {
        int r = g_csr[e];                              // broadcast load
        float coef = tanhf(g_al[r] + arn) * g_dinv[r] * dv;
        float4 v = x4[(size_t)r * D4 + lane];
        acc.x += v.x * coef; acc.y += v.y * coef;
        acc.z += v.z * coef; acc.w += v.w * coef;
    }
    ((float4*)g_agg)[(size_t)n * D4 + lane] = acc;
}

// -------- k6: out = agg @ W + bias  (fp32 SIMT GEMM, 64-row tiles) --------
#define TM 64
__global__ void k_gemm(const float* __restrict__ W,
                       const float* __restrict__ bias,
                       float* __restrict__ out, int N) {
    extern __shared__ float smem[];
    float* Ws = smem;               // 128*128 floats (64 KB)
    float* hs = smem + D * D;       // 64*128 floats (32 KB)
    int tid = threadIdx.x;

    const float4* W4 = (const float4*)W;
    float4* Ws4 = (float4*)Ws;
    #pragma unroll
    for (int i = tid; i < D * D4; i += 256) Ws4[i] = W4[i];

    int m0 = blockIdx.x * TM;
    const float4* h4 = (const float4*)g_agg;
    float4* hs4 = (float4*)hs;
    for (int i = tid; i < TM * D4; i += 256) {
        int row = m0 + (i >> 5);
        hs4[i] = (row < N) ? h4[(size_t)row * D4 + (i & 31)]
                           : make_float4(0.f, 0.f, 0.f, 0.f);
    }
    __syncthreads();

    int w = tid >> 5;       // warp: rows w*8 .. w*8+7 of tile
    int j = tid & 31;       // lane: cols 4j .. 4j+3
    float acc[8][4];
    #pragma unroll
    for (int r = 0; r < 8; r++)
        #pragma unroll
        for (int k = 0; k < 4; k++) acc[r][k] = 0.f;

    #pragma unroll 4
    for (int db = 0; db < D4; db++) {          // blocks of 4 along K
        float4 hv[8];
        #pragma unroll
        for (int r = 0; r < 8; r++) hv[r] = hs4[(w * 8 + r) * D4 + db];
        #pragma unroll
        for (int dd = 0; dd < 4; dd++) {
            float4 wv = Ws4[(db * 4 + dd) * D4 + j];
            #pragma unroll
            for (int r = 0; r < 8; r++) {
                float xv = (dd == 0) ? hv[r].x : (dd == 1) ? hv[r].y
                          : (dd == 2) ? hv[r].z : hv[r].w;
                acc[r][0] += xv * wv.x;
                acc[r][1] += xv * wv.y;
                acc[r][2] += xv * wv.z;
                acc[r][3] += xv * wv.w;
            }
        }
    }

    float4 bv = ((const float4*)bias)[j];
    #pragma unroll
    for (int r = 0; r < 8; r++) {
        int row = m0 + w * 8 + r;
        if (row < N) {
            float4 o = make_float4(acc[r][0] + bv.x, acc[r][1] + bv.y,
                                   acc[r][2] + bv.z, acc[r][3] + bv.w);
            ((float4*)out)[(size_t)row * D4 + j] = o;
        }
    }
}

extern "C" void kernel_launch(void* const* d_in, const int* in_sizes, int n_in,
                              void* d_out, int out_size) {
    const float* x      = (const float*)d_in[0];
    const int*   ep     = (const int*)d_in[1];     // edge buffer as int32 words
    const float* att_l  = (const float*)d_in[2];
    const float* att_r  = (const float*)d_in[3];
    const float* weight = (const float*)d_in[4];
    const float* bias   = (const float*)d_in[5];
    float*       out    = (float*)d_out;

    int N = in_sizes[0] / D;
    int E = in_sizes[1] / 2;   // element count is 2*E under either dtype

    const float4* x4 = (const float4*)x;

    k_zero<<<(N + 255) / 256, 256>>>(N);
    k_probe<<<592, 256>>>((const unsigned int*)ep, E);
    k_setflag<<<1, 1>>>();
    k_count<<<(E + 255) / 256, 256>>>(ep, E);
    k_node<<<(N * 32 + 255) / 256, 256>>>(x4, (const float4*)att_l,
                                          (const float4*)att_r, N);
    k_scan<<<1, 1024>>>(N);
    k_build<<<(E + 255) / 256, 256>>>(ep, E);
    k_gather<<<(N * 32 + 255) / 256, 256>>>(x4, N);
    {
        int smem_bytes = (D * D + TM * D) * sizeof(float);  // 96 KB
        cudaFuncSetAttribute(k_gemm, cudaFuncAttributeMaxDynamicSharedMemorySize,
                             smem_bytes);
        k_gemm<<<(N + TM - 1) / TM, 256, smem_bytes>>>(weight, bias, out, N);
    }
}